// round 15
// baseline (speedup 1.0000x reference)
#include <cuda_runtime.h>
#include <cuda_fp16.h>
#include <cuda_bf16.h>
#include <cstdint>
#include <math.h>

// Problem constants
#define SEQ    2048
#define DMODEL 1024
#define NH     4
#define DHEAD  256
#define NCHUNK 64
#define CSZ    32
#define NQKV   3072

// ---------------- scratch (device globals; allocation-free) ----------------
__device__ __align__(16) float g_qkvlin[SEQ * NQKV];
__device__ __align__(16) float g_q[SEQ * DMODEL];
__device__ __align__(16) float g_k[SEQ * DMODEL];
__device__ __align__(16) float g_v[SEQ * DMODEL];
__device__ __align__(16) float g_u[SEQ * DMODEL];
__device__ __align__(16) float g_w[SEQ * DMODEL];
__device__ __align__(16) float g_delta[SEQ * DMODEL];
__device__ __align__(16) float g_beta[SEQ * NH];
__device__ __align__(16) float g_probs[SEQ * NH * 5];
__device__ __align__(16) float g_attn[NH * NCHUNK * CSZ * CSZ];

// fp16 buffers: activations hi+lo, weights hi only
__device__ __align__(16) __half g_xh[SEQ * DMODEL];
__device__ __align__(16) __half g_xl[SEQ * DMODEL];
__device__ __align__(16) __half g_wqkv[NQKV * DMODEL];
__device__ __align__(16) __half g_wo[DMODEL * DMODEL];
__device__ __align__(16) __half g_mixh[SEQ * DMODEL];
__device__ __align__(16) __half g_mixl[SEQ * DMODEL];

// ---------------- helpers ---------------------------------------------------
__device__ __forceinline__ void mma_f16(float* acc, const unsigned* a,
                                        const unsigned* b) {
    asm volatile(
        "mma.sync.aligned.m16n8k16.row.col.f32.f16.f16.f32 "
        "{%0,%1,%2,%3}, {%4,%5,%6,%7}, {%8,%9}, {%0,%1,%2,%3};"
        : "+f"(acc[0]), "+f"(acc[1]), "+f"(acc[2]), "+f"(acc[3])
        : "r"(a[0]), "r"(a[1]), "r"(a[2]), "r"(a[3]), "r"(b[0]), "r"(b[1]));
}
__device__ __forceinline__ void cp16(unsigned saddr, const void* g) {
    asm volatile("cp.async.cg.shared.global [%0], [%1], 16;"
                 :: "r"(saddr), "l"(g) : "memory");
}
__device__ __forceinline__ void cp4(unsigned saddr, const void* g) {
    asm volatile("cp.async.ca.shared.global [%0], [%1], 4;"
                 :: "r"(saddr), "l"(g) : "memory");
}
__device__ __forceinline__ void ldsm4(unsigned* r, unsigned saddr) {
    asm volatile("ldmatrix.sync.aligned.m8n8.x4.shared.b16 {%0,%1,%2,%3}, [%4];"
                 : "=r"(r[0]), "=r"(r[1]), "=r"(r[2]), "=r"(r[3]) : "r"(saddr));
}

// ---------------- fp16 2-product tensor-core GEMM: C = A * B^T --------------
#define HG_STRIDE 80
#define HG_AT     (128 * HG_STRIDE)
#define HG_BT     (128 * HG_STRIDE)
#define HG_BUFB   (2 * HG_AT + HG_BT)
#define HG_SMEM   (2 * HG_BUFB)

__global__ __launch_bounds__(256, 1) void hgemm_nt(const __half* __restrict__ Ah,
                                                   const __half* __restrict__ Al,
                                                   const __half* __restrict__ Bh,
                                                   float* __restrict__ C,
                                                   int M, int N, int K) {
    extern __shared__ __align__(16) char smem[];
    unsigned sbase;
    asm("{ .reg .u64 t; cvta.to.shared.u64 t, %1; cvt.u32.u64 %0, t; }"
        : "=r"(sbase) : "l"(smem));
    int tid = threadIdx.x;
    int warp = tid >> 5, lane = tid & 31;
    int wm = warp >> 2, wn = warp & 3;
    int g = lane >> 2, t = lane & 3;
    int bm = blockIdx.y * 128, bn = blockIdx.x * 128;

    unsigned lrow8 = (lane & 7) + ((lane >> 3) & 1) * 8;
    unsigned khalf = (lane >> 4) * 16;
    unsigned a_off = (unsigned)((wm * 64 + lrow8) * HG_STRIDE + khalf);
    unsigned b_off = (unsigned)(2 * HG_AT + (wn * 32 + lrow8) * HG_STRIDE + khalf);

    float acc[4][4][4];
#pragma unroll
    for (int mi = 0; mi < 4; mi++)
#pragma unroll
        for (int nj = 0; nj < 4; nj++)
#pragma unroll
            for (int r = 0; r < 4; r++) acc[mi][nj][r] = 0.f;

#define HG_ISSUE(k0, buf)                                                           \
    do {                                                                            \
        unsigned bb = sbase + (buf) * HG_BUFB;                                      \
        _Pragma("unroll")                                                           \
        for (int it = 0; it < 2; it++) {                                            \
            int idx = tid + it * 256;                                               \
            int row = idx >> 2, quad = idx & 3;                                     \
            unsigned so = bb + row * HG_STRIDE + quad * 16;                         \
            size_t ga = (size_t)(bm + row) * K + (k0) + quad * 8;                   \
            cp16(so, Ah + ga);                                                      \
            cp16(so + HG_AT, Al + ga);                                              \
        }                                                                           \
        _Pragma("unroll")                                                           \
        for (int it = 0; it < 2; it++) {                                            \
            int idx = tid + it * 256;                                               \
            int row = idx >> 2, quad = idx & 3;                                     \
            unsigned so = bb + 2 * HG_AT + row * HG_STRIDE + quad * 16;             \
            size_t gb = (size_t)(bn + row) * K + (k0) + quad * 8;                   \
            cp16(so, Bh + gb);                                                      \
        }                                                                           \
        asm volatile("cp.async.commit_group;" ::: "memory");                        \
    } while (0)

    HG_ISSUE(0, 0);

    const int nch = K / 32;
    int buf = 0;
    for (int ch = 0; ch < nch; ch++) {
        if (ch + 1 < nch) {
            HG_ISSUE((ch + 1) * 32, buf ^ 1);
            asm volatile("cp.async.wait_group 1;" ::: "memory");
        } else {
            asm volatile("cp.async.wait_group 0;" ::: "memory");
        }
        __syncthreads();

        unsigned bb = sbase + buf * HG_BUFB;
#pragma unroll
        for (int ks = 0; ks < 2; ks++) {
            unsigned kb = ks * 32;
            unsigned ah[4][4], al[4][4], bq0[4], bq1[4];
#pragma unroll
            for (int mi = 0; mi < 4; mi++) {
                unsigned ad = bb + a_off + mi * (16 * HG_STRIDE) + kb;
                ldsm4(ah[mi], ad);
                ldsm4(al[mi], ad + HG_AT);
            }
            ldsm4(bq0, bb + b_off + kb);
            ldsm4(bq1, bb + b_off + 16 * HG_STRIDE + kb);
            unsigned bf[4][2] = {{bq0[0], bq0[2]}, {bq0[1], bq0[3]},
                                 {bq1[0], bq1[2]}, {bq1[1], bq1[3]}};
#pragma unroll
            for (int mi = 0; mi < 4; mi++)
#pragma unroll
                for (int nj = 0; nj < 4; nj++) {
                    mma_f16(acc[mi][nj], ah[mi], bf[nj]);
                    mma_f16(acc[mi][nj], al[mi], bf[nj]);
                }
        }
        __syncthreads();
        buf ^= 1;
    }

#pragma unroll
    for (int mi = 0; mi < 4; mi++) {
        int row = bm + wm * 64 + mi * 16 + g;
#pragma unroll
        for (int nj = 0; nj < 4; nj++) {
            int col = bn + wn * 32 + nj * 8 + t * 2;
            *(float2*)(C + (size_t)row * N + col) =
                make_float2(acc[mi][nj][0], acc[mi][nj][1]);
            *(float2*)(C + (size_t)(row + 8) * N + col) =
                make_float2(acc[mi][nj][2], acc[mi][nj][3]);
        }
    }
#undef HG_ISSUE
}

// ---------------- fp32 -> fp16 hi/lo split (activations) -------------------
__global__ void split_kernel(const float* __restrict__ in,
                             __half* __restrict__ hi,
                             __half* __restrict__ lo, int n4) {
    int i = blockIdx.x * 256 + threadIdx.x;
    if (i >= n4) return;
    float4 v = ((const float4*)in)[i];
    float vv[4] = {v.x, v.y, v.z, v.w};
    __align__(8) __half h[4];
    __align__(8) __half l[4];
#pragma unroll
    for (int j = 0; j < 4; j++) {
        h[j] = __float2half_rn(vv[j]);
        l[j] = __float2half_rn(vv[j] - __half2float(h[j]));
    }
    ((uint2*)hi)[i] = *(uint2*)h;
    ((uint2*)lo)[i] = *(uint2*)l;
}

// ---------------- weights -> fp16 (hi only), QKV packed --------------------
__global__ void wsplit_kernel(const float* __restrict__ Wq,
                              const float* __restrict__ Wk,
                              const float* __restrict__ Wv,
                              const float* __restrict__ Wo,
                              __half* __restrict__ wqkv,
                              __half* __restrict__ wo) {
    int i = blockIdx.x * 256 + threadIdx.x;
    const int n4 = DMODEL * DMODEL / 4;
    if (i >= n4) return;
    const float* srcs[4] = {Wq, Wk, Wv, Wo};
#pragma unroll
    for (int s = 0; s < 4; s++) {
        float4 v = ((const float4*)srcs[s])[i];
        __align__(8) __half h[4];
        h[0] = __float2half_rn(v.x); h[1] = __float2half_rn(v.y);
        h[2] = __float2half_rn(v.z); h[3] = __float2half_rn(v.w);
        if (s < 3) ((uint2*)wqkv)[s * n4 + i] = *(uint2*)h;
        else       ((uint2*)wo)[i] = *(uint2*)h;
    }
}

// ------- t-tiled conv(K=4)+silu+l2norm; block = (32 timesteps, head) -------
#define CN_T 32
#define CN_R (CN_T + 3)
#define CN_SQ   0
#define CN_SK   (CN_R * 256)
#define CN_SV   (2 * CN_R * 256)
#define CN_QC   (3 * CN_R * 256)
#define CN_KC   (CN_QC + CN_T * 256)
#define CN_RED  (CN_KC + CN_T * 256)
#define CN_SMEM_FLOATS (CN_RED + 64)
__global__ __launch_bounds__(256) void convnorm_kernel(const float* __restrict__ qkvlin,
                                                       const float* __restrict__ wq,
                                                       const float* __restrict__ wk,
                                                       const float* __restrict__ wv,
                                                       float* __restrict__ qb,
                                                       float* __restrict__ kb,
                                                       float* __restrict__ vb) {
    extern __shared__ float cns[];
    int bid = blockIdx.x;
    int h = bid & 3;
    int t0 = (bid >> 2) * CN_T;
    int tid = threadIdx.x;
    int d = tid;
    int c = h * DHEAD + d;

#pragma unroll 3
    for (int p = 0; p < 3; p++) {
        float* dst = cns + p * (CN_R * 256);
        for (int i = tid; i < CN_R * 64; i += 256) {
            int row = i >> 6, d4 = (i & 63) << 2;
            int tt = t0 - 3 + row;
            float4 val = make_float4(0.f, 0.f, 0.f, 0.f);
            if (tt >= 0)
                val = *(const float4*)(qkvlin + (size_t)tt * NQKV + p * DMODEL +
                                       h * DHEAD + d4);
            *(float4*)&dst[row * 256 + d4] = val;
        }
    }
    __syncthreads();

    float wq0 = wq[c * 4], wq1 = wq[c * 4 + 1], wq2 = wq[c * 4 + 2], wq3 = wq[c * 4 + 3];
    float wk0 = wk[c * 4], wk1 = wk[c * 4 + 1], wk2 = wk[c * 4 + 2], wk3 = wk[c * 4 + 3];
    float wv0 = wv[c * 4], wv1 = wv[c * 4 + 1], wv2 = wv[c * 4 + 2], wv3 = wv[c * 4 + 3];

#pragma unroll 4
    for (int t = 0; t < CN_T; t++) {
        const float* sq = cns + CN_SQ + t * 256 + d;
        const float* sk = cns + CN_SK + t * 256 + d;
        const float* sv = cns + CN_SV + t * 256 + d;
        float aq = sq[0] * wq0 + sq[256] * wq1 + sq[512] * wq2 + sq[768] * wq3;
        float ak = sk[0] * wk0 + sk[256] * wk1 + sk[512] * wk2 + sk[768] * wk3;
        float av = sv[0] * wv0 + sv[256] * wv1 + sv[512] * wv2 + sv[768] * wv3;
        float qv = aq / (1.f + expf(-aq));
        float kv = ak / (1.f + expf(-ak));
        float vv = av / (1.f + expf(-av));
        cns[CN_QC + t * 256 + d] = qv;
        cns[CN_KC + t * 256 + d] = kv;
        vb[(size_t)(t0 + t) * DMODEL + c] = vv;
    }
    __syncthreads();

    int lane = tid & 31, warp = tid >> 5;
#pragma unroll
    for (int tt = warp; tt < CN_T; tt += 8) {
        float sq = 0.f, sk = 0.f;
#pragma unroll
        for (int i = lane; i < 256; i += 32) {
            float qv = cns[CN_QC + tt * 256 + i];
            float kv = cns[CN_KC + tt * 256 + i];
            sq = fmaf(qv, qv, sq);
            sk = fmaf(kv, kv, sk);
        }
#pragma unroll
        for (int off = 16; off; off >>= 1) {
            sq += __shfl_xor_sync(0xffffffffu, sq, off);
            sk += __shfl_xor_sync(0xffffffffu, sk, off);
        }
        if (lane == 0) { cns[CN_RED + tt] = sq; cns[CN_RED + 32 + tt] = sk; }
    }
    __syncthreads();

#pragma unroll 4
    for (int t = 0; t < CN_T; t++) {
        float rq = rsqrtf(cns[CN_RED + t] + 1e-6f);
        float rk = rsqrtf(cns[CN_RED + 32 + t] + 1e-6f);
        size_t o = (size_t)(t0 + t) * DMODEL + c;
        qb[o] = cns[CN_QC + t * 256 + d] * rq;
        kb[o] = cns[CN_KC + t * 256 + d] * rk;
    }
}

// ---------------- beta (sigmoid) + gate probs ------------------------------
__global__ void beta_gate_kernel(const float* __restrict__ x,
                                 const float* __restrict__ Wb,
                                 const float* __restrict__ gate_w,
                                 const float* __restrict__ gate_b,
                                 const float* __restrict__ log_temp,
                                 const float* __restrict__ eps_param,
                                 float* __restrict__ beta_out,
                                 float* __restrict__ probs_out) {
    int t = blockIdx.x;
    __shared__ float sx[DMODEL];
    __shared__ float sdot[24];
    int tid = threadIdx.x;
    for (int i = tid; i < DMODEL; i += 256) sx[i] = x[t * DMODEL + i];
    __syncthreads();
    int warp = tid >> 5, lane = tid & 31;
    for (int o = warp; o < 24; o += 8) {
        const float* wrow = (o < 4) ? (Wb + o * DMODEL) : (gate_w + (o - 4) * DMODEL);
        float s = 0.f;
        for (int i = lane; i < DMODEL; i += 32) s += sx[i] * wrow[i];
#pragma unroll
        for (int off = 16; off; off >>= 1) s += __shfl_xor_sync(0xffffffffu, s, off);
        if (lane == 0) sdot[o] = s;
    }
    __syncthreads();
    if (tid < NH) {
        int h = tid;
        beta_out[t * NH + h] = 1.f / (1.f + expf(-sdot[h]));
        float temp = expf(log_temp[h]);
        float lg[5], mx = -1e30f;
#pragma unroll
        for (int p = 0; p < 5; p++) {
            lg[p] = (sdot[4 + h * 5 + p] + gate_b[h * 5 + p]) / temp;
            mx = fmaxf(mx, lg[p]);
        }
        float se = 0.f;
#pragma unroll
        for (int p = 0; p < 5; p++) { lg[p] = expf(lg[p] - mx); se += lg[p]; }
        float eps = fminf(fmaxf(eps_param[h], 0.f), 0.2f);
#pragma unroll
        for (int p = 0; p < 5; p++)
            probs_out[(t * NH + h) * 5 + p] = lg[p] / se * (1.f - 5.f * eps) + eps;
    }
}

// ---------------- per-chunk UT transform (parallel over chunks) ------------
#define CP_SMEM_FLOATS (2 * 32 * 260 + 2 * 32 * 33 + 32)
__global__ __launch_bounds__(256) void chunk_prep_kernel(const float* __restrict__ q,
                                                         const float* __restrict__ k,
                                                         const float* __restrict__ v,
                                                         const float* __restrict__ beta,
                                                         float* __restrict__ gu,
                                                         float* __restrict__ gw,
                                                         float* __restrict__ gattn) {
    extern __shared__ float smemf[];
    float (*sk)[260] = (float (*)[260])smemf;
    float (*sx)[260] = (float (*)[260])(smemf + 32 * 260);
    float (*sA)[33]  = (float (*)[33])(smemf + 2 * 32 * 260);
    float (*sT)[33]  = (float (*)[33])(smemf + 2 * 32 * 260 + 32 * 33);
    float* sbeta     = smemf + 2 * 32 * 260 + 2 * 32 * 33;

    int hb = blockIdx.x;
    int h = hb >> 6, ch = hb & 63;
    int t0 = ch * CSZ;
    int tid = threadIdx.x;

#pragma unroll
    for (int it = 0; it < 8; it++) {
        int i4 = tid + it * 256;
        int row = i4 >> 6, d4 = (i4 & 63) << 2;
        *(float4*)&sk[row][d4] =
            *(const float4*)(k + (size_t)(t0 + row) * DMODEL + h * DHEAD + d4);
    }
    if (tid < CSZ) sbeta[tid] = beta[(t0 + tid) * NH + h];
    __syncthreads();

#pragma unroll
    for (int p = tid; p < CSZ * CSZ; p += 256) {
        int i = p >> 5, j = p & 31;
        float a = 0.f;
        if (j < i) {
            float s0 = 0.f, s1 = 0.f;
#pragma unroll 8
            for (int d8 = 0; d8 < DHEAD; d8 += 8) {
                float4 x0 = *(const float4*)&sk[i][d8];
                float4 y0 = *(const float4*)&sk[j][d8];
                float4 x1 = *(const float4*)&sk[i][d8 + 4];
                float4 y1 = *(const float4*)&sk[j][d8 + 4];
                s0 = fmaf(x0.x, y0.x, fmaf(x0.y, y0.y,
                     fmaf(x0.z, y0.z, fmaf(x0.w, y0.w, s0))));
                s1 = fmaf(x1.x, y1.x, fmaf(x1.y, y1.y,
                     fmaf(x1.z, y1.z, fmaf(x1.w, y1.w, s1))));
            }
            a = -sbeta[i] * (s0 + s1);
        }
        sA[i][j] = a;
    }
    __syncthreads();

    if (tid < 32) {
        int col = tid;
        for (int i = 0; i < CSZ; i++) {
            float tv = (col == i) ? 1.f : 0.f;
            for (int j = 0; j < i; j++) tv += sA[i][j] * sT[j][col];
            sT[i][col] = tv;
            __syncwarp();
        }
    }
    __syncthreads();

#pragma unroll
    for (int it = 0; it < 8; it++) {
        int i4 = tid + it * 256;
        int row = i4 >> 6, d4 = (i4 & 63) << 2;
        float4 vv = *(const float4*)(v + (size_t)(t0 + row) * DMODEL + h * DHEAD + d4);
        float bb = sbeta[row];
        vv.x *= bb; vv.y *= bb; vv.z *= bb; vv.w *= bb;
        *(float4*)&sx[row][d4] = vv;
    }
    __syncthreads();

    {
        int d = tid;
        float acc[32];
#pragma unroll
        for (int i = 0; i < 32; i++) acc[i] = 0.f;
#pragma unroll
        for (int j = 0; j < 32; j++) {
            float xv = sx[j][d];
#pragma unroll
            for (int i = j; i < 32; i++) acc[i] = fmaf(sT[i][j], xv, acc[i]);
        }
#pragma unroll
        for (int i = 0; i < 32; i++)
            gu[(t0 + i) * DMODEL + h * DHEAD + d] = acc[i];
#pragma unroll
        for (int i = 0; i < 32; i++) acc[i] = 0.f;
#pragma unroll
        for (int j = 0; j < 32; j++) {
            float xv = sbeta[j] * sk[j][d];
#pragma unroll
            for (int i = j; i < 32; i++) acc[i] = fmaf(sT[i][j], xv, acc[i]);
        }
#pragma unroll
        for (int i = 0; i < 32; i++)
            gw[(t0 + i) * DMODEL + h * DHEAD + d] = acc[i];
    }
    __syncthreads();

#pragma unroll
    for (int it = 0; it < 8; it++) {
        int i4 = tid + it * 256;
        int row = i4 >> 6, d4 = (i4 & 63) << 2;
        *(float4*)&sx[row][d4] =
            *(const float4*)(q + (size_t)(t0 + row) * DMODEL + h * DHEAD + d4);
    }
    __syncthreads();
#pragma unroll
    for (int p = tid; p < CSZ * CSZ; p += 256) {
        int i = p >> 5, j = p & 31;
        float a = 0.f;
        if (j <= i) {
            float s0 = 0.f, s1 = 0.f;
#pragma unroll 8
            for (int d8 = 0; d8 < DHEAD; d8 += 8) {
                float4 x0 = *(const float4*)&sx[i][d8];
                float4 y0 = *(const float4*)&sk[j][d8];
                float4 x1 = *(const float4*)&sx[i][d8 + 4];
                float4 y1 = *(const float4*)&sk[j][d8 + 4];
                s0 = fmaf(x0.x, y0.x, fmaf(x0.y, y0.y,
                     fmaf(x0.z, y0.z, fmaf(x0.w, y0.w, s0))));
                s1 = fmaf(x1.x, y1.x, fmaf(x1.y, y1.y,
                     fmaf(x1.z, y1.z, fmaf(x1.w, y1.w, s1))));
            }
            a = s0 + s1;
        }
        gattn[(hb * CSZ + i) * CSZ + j] = a;
    }
}

// -- sequential chunk scan v7: slice width 16, 64 blocks x 512 threads ------
// Halves q/k/w tile broadcast redundancy vs width-8 (L2 traffic 800->400 MB).
#define SD_TILE   (32 * 260)
#define SD_BUF    (3 * SD_TILE)
#define SD_SC     (2 * SD_BUF)               // Sc[16][260]
#define SD_SU     (SD_SC + 16 * 260)         // su 2x512
#define SD_SATT   (SD_SU + 2 * 512)          // satt 2x1024
#define SD_SUA    (SD_SATT + 2 * 1024)       // sua 512
#define SCAN_SMEM_FLOATS (SD_SUA + 512)      // 57664 floats = 230656 B
__global__ __launch_bounds__(512) void delta_scan_kernel(const float* __restrict__ q,
                                                         const float* __restrict__ k,
                                                         const float* __restrict__ w,
                                                         const float* __restrict__ u,
                                                         const float* __restrict__ attn,
                                                         float* __restrict__ dout) {
    extern __shared__ float smemf[];
    unsigned sb;
    asm("{ .reg .u64 t; cvta.to.shared.u64 t, %1; cvt.u32.u64 %0, t; }"
        : "=r"(sb) : "l"(smemf));

    int b = blockIdx.x;               // 0..63
    int h = b >> 4, sl = b & 15;
    int tid = threadIdx.x;            // 0..511
    int r = tid >> 4, c = tid & 15;   // output element (row, col)
    int dk = tid >> 1, half8 = (tid & 1) * 8;   // S ownership
    int cbase = h * DHEAD + sl * 16;

#define SD_ISSUE(ch, bf)                                                            \
    do {                                                                            \
        int t0i = (ch) * CSZ;                                                       \
        unsigned qo = sb + ((bf) * SD_BUF) * 4;                                     \
        _Pragma("unroll")                                                           \
        for (int it = 0; it < 4; it++) {                                            \
            int i4 = tid + it * 512;                                                \
            int row = i4 >> 6, d4 = (i4 & 63) << 2;                                 \
            size_t gidx = (size_t)(t0i + row) * DMODEL + h * DHEAD + d4;            \
            unsigned so = qo + (row * 260 + d4) * 4;                                \
            cp16(so, q + gidx);                                                     \
            cp16(so + SD_TILE * 4, k + gidx);                                       \
            cp16(so + 2 * SD_TILE * 4, w + gidx);                                   \
        }                                                                           \
        cp4(sb + (SD_SU + (bf) * 512 + tid) * 4,                                    \
            u + (size_t)(t0i + r) * DMODEL + cbase + c);                            \
        if (tid < 256)                                                              \
            cp16(sb + (SD_SATT + (bf) * 1024 + tid * 4) * 4,                        \
                 attn + (size_t)(h * NCHUNK + (ch)) * 1024 + tid * 4);              \
        asm volatile("cp.async.commit_group;" ::: "memory");                        \
    } while (0)

    float Sreg[8];
#pragma unroll
    for (int i = 0; i < 8; i++) Sreg[i] = 0.f;

    SD_ISSUE(0, 0);
    int buf = 0;
    for (int ch = 0; ch < NCHUNK; ch++) {
        // publish S: thread owns S[dk][half8..half8+8) -> Sc[col][dk]
#pragma unroll
        for (int i = 0; i < 8; i++)
            smemf[SD_SC + (half8 + i) * 260 + dk] = Sreg[i];
        if (ch + 1 < NCHUNK) {
            SD_ISSUE(ch + 1, buf ^ 1);
            asm volatile("cp.async.wait_group 1;" ::: "memory");
        } else {
            asm volatile("cp.async.wait_group 0;" ::: "memory");
        }
        __syncthreads();

        const float* sq  = smemf + buf * SD_BUF;
        const float* skk = sq + SD_TILE;
        const float* sw  = sq + 2 * SD_TILE;
        const float* su  = smemf + SD_SU + buf * 512;
        const float* satt = smemf + SD_SATT + buf * 1024;
        float* sua = smemf + SD_SUA;

        // u_adj = u - w@S ; o = q@S ; 4 chains each (same as v5)
        float au0 = 0.f, au1 = 0.f, au2 = 0.f, au3 = 0.f;
        float ao0 = 0.f, ao1 = 0.f, ao2 = 0.f, ao3 = 0.f;
        const float* scc = smemf + SD_SC + c * 260;
        const float* swr = sw + r * 260;
        const float* sqr = sq + r * 260;
#pragma unroll 4
        for (int d16 = 0; d16 < DHEAD; d16 += 16) {
            float4 sv0 = *(const float4*)&scc[d16];
            float4 wv0 = *(const float4*)&swr[d16];
            float4 qv0 = *(const float4*)&sqr[d16];
            float4 sv1 = *(const float4*)&scc[d16 + 4];
            float4 wv1 = *(const float4*)&swr[d16 + 4];
            float4 qv1 = *(const float4*)&sqr[d16 + 4];
            float4 sv2 = *(const float4*)&scc[d16 + 8];
            float4 wv2 = *(const float4*)&swr[d16 + 8];
            float4 qv2 = *(const float4*)&sqr[d16 + 8];
            float4 sv3 = *(const float4*)&scc[d16 + 12];
            float4 wv3 = *(const float4*)&swr[d16 + 12];
            float4 qv3 = *(const float4*)&sqr[d16 + 12];
            au0 = fmaf(wv0.x, sv0.x, fmaf(wv0.y, sv0.y,
                  fmaf(wv0.z, sv0.z, fmaf(wv0.w, sv0.w, au0))));
            au1 = fmaf(wv1.x, sv1.x, fmaf(wv1.y, sv1.y,
                  fmaf(wv1.z, sv1.z, fmaf(wv1.w, sv1.w, au1))));
            au2 = fmaf(wv2.x, sv2.x, fmaf(wv2.y, sv2.y,
                  fmaf(wv2.z, sv2.z, fmaf(wv2.w, sv2.w, au2))));
            au3 = fmaf(wv3.x, sv3.x, fmaf(wv3.y, sv3.y,
                  fmaf(wv3.z, sv3.z, fmaf(wv3.w, sv3.w, au3))));
            ao0 = fmaf(qv0.x, sv0.x, fmaf(qv0.y, sv0.y,
                  fmaf(qv0.z, sv0.z, fmaf(qv0.w, sv0.w, ao0))));
            ao1 = fmaf(qv1.x, sv1.x, fmaf(qv1.y, sv1.y,
                  fmaf(qv1.z, sv1.z, fmaf(qv1.w, sv1.w, ao1))));
            ao2 = fmaf(qv2.x, sv2.x, fmaf(qv2.y, sv2.y,
                  fmaf(qv2.z, sv2.z, fmaf(qv2.w, sv2.w, ao2))));
            ao3 = fmaf(qv3.x, sv3.x, fmaf(qv3.y, sv3.y,
                  fmaf(qv3.z, sv3.z, fmaf(qv3.w, sv3.w, ao3))));
        }
        float au = su[tid] - ((au0 + au1) + (au2 + au3));
        float ao = (ao0 + ao1) + (ao2 + ao3);
        sua[tid] = au;      // sua[r*16 + c] == sua[tid]
        __syncthreads();

#pragma unroll
        for (int j4 = 0; j4 < CSZ; j4 += 4) {
            float4 at = *(const float4*)&satt[r * CSZ + j4];
            ao = fmaf(at.x, sua[(j4 + 0) * 16 + c], ao);
            ao = fmaf(at.y, sua[(j4 + 1) * 16 + c], ao);
            ao = fmaf(at.z, sua[(j4 + 2) * 16 + c], ao);
            ao = fmaf(at.w, sua[(j4 + 3) * 16 + c], ao);
        }
        dout[(size_t)(ch * CSZ + r) * DMODEL + cbase + c] = ao;

        // S += k^T @ u_adj ; thread owns S[dk][half8..half8+8)
#pragma unroll 8
        for (int j = 0; j < CSZ; j++) {
            float kv = skk[j * 260 + dk];
            float4 u0 = *(const float4*)&sua[j * 16 + half8];
            float4 u1 = *(const float4*)&sua[j * 16 + half8 + 4];
            Sreg[0] = fmaf(kv, u0.x, Sreg[0]);
            Sreg[1] = fmaf(kv, u0.y, Sreg[1]);
            Sreg[2] = fmaf(kv, u0.z, Sreg[2]);
            Sreg[3] = fmaf(kv, u0.w, Sreg[3]);
            Sreg[4] = fmaf(kv, u1.x, Sreg[4]);
            Sreg[5] = fmaf(kv, u1.y, Sreg[5]);
            Sreg[6] = fmaf(kv, u1.z, Sreg[6]);
            Sreg[7] = fmaf(kv, u1.w, Sreg[7]);
        }
        __syncthreads();
        buf ^= 1;
    }
#undef SD_ISSUE
}

// ---------------- FIR + gated mix + RMSNorm, t-tiled; fp16 hi/lo output ----
#define CT 16
#define VR (CT + 62)
#define CMB_SMEM_FLOATS (256 * 81 + 256 * 81 + 80 + 4096 + 16)
__global__ __launch_bounds__(256) void combine_kernel(const float* __restrict__ v,
                                                      const float* __restrict__ delta,
                                                      const float* __restrict__ probs,
                                                      const float* __restrict__ fs,
                                                      const float* __restrict__ fm,
                                                      const float* __restrict__ fl,
                                                      const float* __restrict__ normw,
                                                      __half* __restrict__ outh,
                                                      __half* __restrict__ outl) {
    extern __shared__ float cs[];
    float (*vsm)[81] = (float (*)[81])cs;
    float (*fsm)[81] = (float (*)[81])(cs + 256 * 81);
    float* psm = cs + 2 * 256 * 81;
    float* sqm = psm + 80;
    float* red = sqm + 4096;

    int bid = blockIdx.x;
    int h = bid & 3;
    int tt0 = (bid >> 2) * CT;
    int tid = threadIdx.x;
    int d = tid;

    const float* flh = fl + h * 256 * 63;
    for (int f = tid; f < 256 * 63; f += 256) {
        int dd = f / 63;
        fsm[dd][f - dd * 63] = flh[f];
    }
    const float* fmh = fm + h * 256 * 15;
    for (int f = tid; f < 256 * 15; f += 256) {
        int dd = f / 15;
        fsm[dd][63 + f - dd * 15] = fmh[f];
    }
    const float* fsh = fs + h * 256 * 3;
    for (int f = tid; f < 256 * 3; f += 256) {
        int dd = f / 3;
        fsm[dd][78 + f - dd * 3] = fsh[f];
    }
    if (tid < CT * 5)
        psm[tid] = probs[(tt0 * NH + h) * 5 + (tid / 5) * (NH * 5) + (tid % 5)];
    for (int L = 0; L < VR; L++) {
        int tt = tt0 - 62 + L;
        vsm[tid][L] = (tt >= 0) ? v[(size_t)tt * DMODEL + h * DHEAD + tid] : 0.f;
    }
    __syncthreads();

    float aL[CT], aM[CT], aS[CT];
#pragma unroll
    for (int t = 0; t < CT; t++) { aL[t] = 0.f; aM[t] = 0.f; aS[t] = 0.f; }

    for (int kk = 0; kk < 63; kk++) {
        float fv = fsm[d][kk];
#pragma unroll
        for (int t = 0; t < CT; t++) aL[t] = fmaf(vsm[d][kk + t], fv, aL[t]);
    }
#pragma unroll
    for (int kk = 0; kk < 15; kk++) {
        float fv = fsm[d][63 + kk];
#pragma unroll
        for (int t = 0; t < CT; t++) aM[t] = fmaf(vsm[d][48 + kk + t], fv, aM[t]);
    }
#pragma unroll
    for (int kk = 0; kk < 3; kk++) {
        float fv = fsm[d][78 + kk];
#pragma unroll
        for (int t = 0; t < CT; t++) aS[t] = fmaf(vsm[d][60 + kk + t], fv, aS[t]);
    }

    float mixv[CT];
#pragma unroll
    for (int t = 0; t < CT; t++) {
        float dlv = delta[(size_t)(tt0 + t) * DMODEL + h * DHEAD + d];
        const float* pb = psm + t * 5;
        float vcur = vsm[d][62 + t];
        mixv[t] = pb[0] * aS[t] + pb[1] * aM[t] + pb[2] * aL[t] +
                  pb[3] * dlv + pb[4] * vcur;
        sqm[t * 256 + d] = mixv[t] * mixv[t];
    }
    __syncthreads();

    int lane = tid & 31, warp = tid >> 5;
#pragma unroll
    for (int tt = warp; tt < CT; tt += 8) {
        float s = 0.f;
#pragma unroll
        for (int i = lane; i < 256; i += 32) s += sqm[tt * 256 + i];
#pragma unroll
        for (int off = 16; off; off >>= 1) s += __shfl_xor_sync(0xffffffffu, s, off);
        if (lane == 0) red[tt] = s;
    }
    __syncthreads();

    float nw = normw[d];
#pragma unroll
    for (int t = 0; t < CT; t++) {
        float val = mixv[t] * rsqrtf(red[t] * (1.f / 256.f) + 1e-5f) * nw;
        __half hv = __float2half_rn(val);
        size_t o = (size_t)(tt0 + t) * DMODEL + h * DHEAD + d;
        outh[o] = hv;
        outl[o] = __float2half_rn(val - __half2float(hv));
    }
}

// ---------------- launch ---------------------------------------------------
extern "C" void kernel_launch(void* const* d_in, const int* in_sizes, int n_in,
                              void* d_out, int out_size) {
    const float* x       = (const float*)d_in[0];
    const float* Wq      = (const float*)d_in[1];
    const float* Wk      = (const float*)d_in[2];
    const float* Wv      = (const float*)d_in[3];
    const float* Wb      = (const float*)d_in[4];
    const float* conv_q  = (const float*)d_in[5];
    const float* conv_k  = (const float*)d_in[6];
    const float* conv_v  = (const float*)d_in[7];
    const float* fir_s   = (const float*)d_in[8];
    const float* fir_m   = (const float*)d_in[9];
    const float* fir_l   = (const float*)d_in[10];
    const float* gate_w  = (const float*)d_in[11];
    const float* gate_b  = (const float*)d_in[12];
    const float* log_tmp = (const float*)d_in[13];
    const float* eps_p   = (const float*)d_in[14];
    const float* norm_w  = (const float*)d_in[15];
    const float* Wo      = (const float*)d_in[16];
    float* out = (float*)d_out;

    float *qkvlin, *qb, *kb, *vb, *ub, *wb, *db, *betab, *probsb, *attnb;
    cudaGetSymbolAddress((void**)&qkvlin, g_qkvlin);
    cudaGetSymbolAddress((void**)&qb,    g_q);
    cudaGetSymbolAddress((void**)&kb,    g_k);
    cudaGetSymbolAddress((void**)&vb,    g_v);
    cudaGetSymbolAddress((void**)&ub,    g_u);
    cudaGetSymbolAddress((void**)&wb,    g_w);
    cudaGetSymbolAddress((void**)&db,    g_delta);
    cudaGetSymbolAddress((void**)&betab, g_beta);
    cudaGetSymbolAddress((void**)&probsb, g_probs);
    cudaGetSymbolAddress((void**)&attnb, g_attn);

    __half *xh, *xl, *wqkv, *wo, *mixh, *mixl;
    cudaGetSymbolAddress((void**)&xh, g_xh);
    cudaGetSymbolAddress((void**)&xl, g_xl);
    cudaGetSymbolAddress((void**)&wqkv, g_wqkv);
    cudaGetSymbolAddress((void**)&wo, g_wo);
    cudaGetSymbolAddress((void**)&mixh, g_mixh);
    cudaGetSymbolAddress((void**)&mixl, g_mixl);

    cudaFuncSetAttribute(hgemm_nt, cudaFuncAttributeMaxDynamicSharedMemorySize, HG_SMEM);
    cudaFuncSetAttribute(convnorm_kernel, cudaFuncAttributeMaxDynamicSharedMemorySize,
                         CN_SMEM_FLOATS * 4);
    cudaFuncSetAttribute(chunk_prep_kernel, cudaFuncAttributeMaxDynamicSharedMemorySize,
                         CP_SMEM_FLOATS * 4);
    cudaFuncSetAttribute(delta_scan_kernel, cudaFuncAttributeMaxDynamicSharedMemorySize,
                         SCAN_SMEM_FLOATS * 4);
    cudaFuncSetAttribute(combine_kernel, cudaFuncAttributeMaxDynamicSharedMemorySize,
                         CMB_SMEM_FLOATS * 4);

    int nX4 = SEQ * DMODEL / 4;
    int nW4 = DMODEL * DMODEL / 4;

    split_kernel<<<(nX4 + 255) / 256, 256>>>(x, xh, xl, nX4);                 // 0
    wsplit_kernel<<<(nW4 + 255) / 256, 256>>>(Wq, Wk, Wv, Wo, wqkv, wo);      // 1
    dim3 tg3(NQKV / 128, SEQ / 128);                                          // (24,16)
    hgemm_nt<<<tg3, 256, HG_SMEM>>>(xh, xl, wqkv, qkvlin, SEQ, NQKV, DMODEL); // 2
    convnorm_kernel<<<(SEQ / CN_T) * NH, 256, CN_SMEM_FLOATS * 4>>>(
        qkvlin, conv_q, conv_k, conv_v, qb, kb, vb);                          // 3 (ncu)
    beta_gate_kernel<<<SEQ, 256>>>(x, Wb, gate_w, gate_b, log_tmp, eps_p,
                                   betab, probsb);                            // 4
    chunk_prep_kernel<<<NH * NCHUNK, 256, CP_SMEM_FLOATS * 4>>>(qb, kb, vb, betab,
                                                                ub, wb, attnb);
    delta_scan_kernel<<<NH * 16, 512, SCAN_SMEM_FLOATS * 4>>>(qb, kb, wb, ub,
                                                              attnb, db);
    combine_kernel<<<(SEQ / CT) * NH, 256, CMB_SMEM_FLOATS * 4>>>(
        vb, db, probsb, fir_s, fir_m, fir_l, norm_w, mixh, mixl);
    dim3 tg1(DMODEL / 128, SEQ / 128);                                        // (8,16)
    hgemm_nt<<<tg1, 256, HG_SMEM>>>(mixh, mixl, wo, out, SEQ, DMODEL, DMODEL);
}

// round 16
// speedup vs baseline: 1.3199x; 1.3199x over previous
#include <cuda_runtime.h>
#include <cuda_fp16.h>
#include <cuda_bf16.h>
#include <cstdint>
#include <math.h>

// Problem constants
#define SEQ    2048
#define DMODEL 1024
#define NH     4
#define DHEAD  256
#define NCHUNK 64
#define CSZ    32
#define NQKV   3072

// ---------------- scratch (device globals; allocation-free) ----------------
__device__ __align__(16) float g_qkvlin[SEQ * NQKV];
__device__ __align__(16) float g_q[SEQ * DMODEL];
__device__ __align__(16) float g_k[SEQ * DMODEL];
__device__ __align__(16) float g_v[SEQ * DMODEL];
__device__ __align__(16) float g_u[SEQ * DMODEL];
__device__ __align__(16) float g_w[SEQ * DMODEL];
__device__ __align__(16) float g_delta[SEQ * DMODEL];
__device__ __align__(16) float g_beta[SEQ * NH];
__device__ __align__(16) float g_probs[SEQ * NH * 5];
__device__ __align__(16) float g_attn[NH * NCHUNK * CSZ * CSZ];

// fp16 buffers: activations hi+lo, weights hi only
__device__ __align__(16) __half g_xh[SEQ * DMODEL];
__device__ __align__(16) __half g_xl[SEQ * DMODEL];
__device__ __align__(16) __half g_wqkv[NQKV * DMODEL];
__device__ __align__(16) __half g_wo[DMODEL * DMODEL];
__device__ __align__(16) __half g_mixh[SEQ * DMODEL];
__device__ __align__(16) __half g_mixl[SEQ * DMODEL];

// ---------------- helpers ---------------------------------------------------
__device__ __forceinline__ void mma_f16(float* acc, const unsigned* a,
                                        const unsigned* b) {
    asm volatile(
        "mma.sync.aligned.m16n8k16.row.col.f32.f16.f16.f32 "
        "{%0,%1,%2,%3}, {%4,%5,%6,%7}, {%8,%9}, {%0,%1,%2,%3};"
        : "+f"(acc[0]), "+f"(acc[1]), "+f"(acc[2]), "+f"(acc[3])
        : "r"(a[0]), "r"(a[1]), "r"(a[2]), "r"(a[3]), "r"(b[0]), "r"(b[1]));
}
__device__ __forceinline__ void cp16(unsigned saddr, const void* g) {
    asm volatile("cp.async.cg.shared.global [%0], [%1], 16;"
                 :: "r"(saddr), "l"(g) : "memory");
}
__device__ __forceinline__ void cp4(unsigned saddr, const void* g) {
    asm volatile("cp.async.ca.shared.global [%0], [%1], 4;"
                 :: "r"(saddr), "l"(g) : "memory");
}
__device__ __forceinline__ void ldsm4(unsigned* r, unsigned saddr) {
    asm volatile("ldmatrix.sync.aligned.m8n8.x4.shared.b16 {%0,%1,%2,%3}, [%4];"
                 : "=r"(r[0]), "=r"(r[1]), "=r"(r[2]), "=r"(r[3]) : "r"(saddr));
}

// ---------------- fp16 2-product tensor-core GEMM: C = A * B^T --------------
#define HG_STRIDE 80
#define HG_AT     (128 * HG_STRIDE)
#define HG_BT     (128 * HG_STRIDE)
#define HG_BUFB   (2 * HG_AT + HG_BT)
#define HG_SMEM   (2 * HG_BUFB)

__global__ __launch_bounds__(256, 1) void hgemm_nt(const __half* __restrict__ Ah,
                                                   const __half* __restrict__ Al,
                                                   const __half* __restrict__ Bh,
                                                   float* __restrict__ C,
                                                   int M, int N, int K) {
    extern __shared__ __align__(16) char smem[];
    unsigned sbase;
    asm("{ .reg .u64 t; cvta.to.shared.u64 t, %1; cvt.u32.u64 %0, t; }"
        : "=r"(sbase) : "l"(smem));
    int tid = threadIdx.x;
    int warp = tid >> 5, lane = tid & 31;
    int wm = warp >> 2, wn = warp & 3;
    int g = lane >> 2, t = lane & 3;
    int bm = blockIdx.y * 128, bn = blockIdx.x * 128;

    unsigned lrow8 = (lane & 7) + ((lane >> 3) & 1) * 8;
    unsigned khalf = (lane >> 4) * 16;
    unsigned a_off = (unsigned)((wm * 64 + lrow8) * HG_STRIDE + khalf);
    unsigned b_off = (unsigned)(2 * HG_AT + (wn * 32 + lrow8) * HG_STRIDE + khalf);

    float acc[4][4][4];
#pragma unroll
    for (int mi = 0; mi < 4; mi++)
#pragma unroll
        for (int nj = 0; nj < 4; nj++)
#pragma unroll
            for (int r = 0; r < 4; r++) acc[mi][nj][r] = 0.f;

#define HG_ISSUE(k0, buf)                                                           \
    do {                                                                            \
        unsigned bb = sbase + (buf) * HG_BUFB;                                      \
        _Pragma("unroll")                                                           \
        for (int it = 0; it < 2; it++) {                                            \
            int idx = tid + it * 256;                                               \
            int row = idx >> 2, quad = idx & 3;                                     \
            unsigned so = bb + row * HG_STRIDE + quad * 16;                         \
            size_t ga = (size_t)(bm + row) * K + (k0) + quad * 8;                   \
            cp16(so, Ah + ga);                                                      \
            cp16(so + HG_AT, Al + ga);                                              \
        }                                                                           \
        _Pragma("unroll")                                                           \
        for (int it = 0; it < 2; it++) {                                            \
            int idx = tid + it * 256;                                               \
            int row = idx >> 2, quad = idx & 3;                                     \
            unsigned so = bb + 2 * HG_AT + row * HG_STRIDE + quad * 16;             \
            size_t gb = (size_t)(bn + row) * K + (k0) + quad * 8;                   \
            cp16(so, Bh + gb);                                                      \
        }                                                                           \
        asm volatile("cp.async.commit_group;" ::: "memory");                        \
    } while (0)

    HG_ISSUE(0, 0);

    const int nch = K / 32;
    int buf = 0;
    for (int ch = 0; ch < nch; ch++) {
        if (ch + 1 < nch) {
            HG_ISSUE((ch + 1) * 32, buf ^ 1);
            asm volatile("cp.async.wait_group 1;" ::: "memory");
        } else {
            asm volatile("cp.async.wait_group 0;" ::: "memory");
        }
        __syncthreads();

        unsigned bb = sbase + buf * HG_BUFB;
#pragma unroll
        for (int ks = 0; ks < 2; ks++) {
            unsigned kb = ks * 32;
            unsigned ah[4][4], al[4][4], bq0[4], bq1[4];
#pragma unroll
            for (int mi = 0; mi < 4; mi++) {
                unsigned ad = bb + a_off + mi * (16 * HG_STRIDE) + kb;
                ldsm4(ah[mi], ad);
                ldsm4(al[mi], ad + HG_AT);
            }
            ldsm4(bq0, bb + b_off + kb);
            ldsm4(bq1, bb + b_off + 16 * HG_STRIDE + kb);
            unsigned bf[4][2] = {{bq0[0], bq0[2]}, {bq0[1], bq0[3]},
                                 {bq1[0], bq1[2]}, {bq1[1], bq1[3]}};
#pragma unroll
            for (int mi = 0; mi < 4; mi++)
#pragma unroll
                for (int nj = 0; nj < 4; nj++) {
                    mma_f16(acc[mi][nj], ah[mi], bf[nj]);
                    mma_f16(acc[mi][nj], al[mi], bf[nj]);
                }
        }
        __syncthreads();
        buf ^= 1;
    }

#pragma unroll
    for (int mi = 0; mi < 4; mi++) {
        int row = bm + wm * 64 + mi * 16 + g;
#pragma unroll
        for (int nj = 0; nj < 4; nj++) {
            int col = bn + wn * 32 + nj * 8 + t * 2;
            *(float2*)(C + (size_t)row * N + col) =
                make_float2(acc[mi][nj][0], acc[mi][nj][1]);
            *(float2*)(C + (size_t)(row + 8) * N + col) =
                make_float2(acc[mi][nj][2], acc[mi][nj][3]);
        }
    }
#undef HG_ISSUE
}

// ---------------- fp32 -> fp16 hi/lo split (activations) -------------------
__global__ void split_kernel(const float* __restrict__ in,
                             __half* __restrict__ hi,
                             __half* __restrict__ lo, int n4) {
    int i = blockIdx.x * 256 + threadIdx.x;
    if (i >= n4) return;
    float4 v = ((const float4*)in)[i];
    float vv[4] = {v.x, v.y, v.z, v.w};
    __align__(8) __half h[4];
    __align__(8) __half l[4];
#pragma unroll
    for (int j = 0; j < 4; j++) {
        h[j] = __float2half_rn(vv[j]);
        l[j] = __float2half_rn(vv[j] - __half2float(h[j]));
    }
    ((uint2*)hi)[i] = *(uint2*)h;
    ((uint2*)lo)[i] = *(uint2*)l;
}

// ---------------- weights -> fp16 (hi only), QKV packed --------------------
__global__ void wsplit_kernel(const float* __restrict__ Wq,
                              const float* __restrict__ Wk,
                              const float* __restrict__ Wv,
                              const float* __restrict__ Wo,
                              __half* __restrict__ wqkv,
                              __half* __restrict__ wo) {
    int i = blockIdx.x * 256 + threadIdx.x;
    const int n4 = DMODEL * DMODEL / 4;
    if (i >= n4) return;
    const float* srcs[4] = {Wq, Wk, Wv, Wo};
#pragma unroll
    for (int s = 0; s < 4; s++) {
        float4 v = ((const float4*)srcs[s])[i];
        __align__(8) __half h[4];
        h[0] = __float2half_rn(v.x); h[1] = __float2half_rn(v.y);
        h[2] = __float2half_rn(v.z); h[3] = __float2half_rn(v.w);
        if (s < 3) ((uint2*)wqkv)[s * n4 + i] = *(uint2*)h;
        else       ((uint2*)wo)[i] = *(uint2*)h;
    }
}

// ------- t-tiled conv(K=4)+silu+l2norm; block = (16 timesteps, head) -------
#define CN_T 16
#define CN_R (CN_T + 3)
#define CN_SQ   0
#define CN_SK   (CN_R * 256)
#define CN_SV   (2 * CN_R * 256)
#define CN_QC   (3 * CN_R * 256)
#define CN_KC   (CN_QC + CN_T * 256)
#define CN_RED  (CN_KC + CN_T * 256)
#define CN_SMEM_FLOATS (CN_RED + 64)
__global__ __launch_bounds__(256) void convnorm_kernel(const float* __restrict__ qkvlin,
                                                       const float* __restrict__ wq,
                                                       const float* __restrict__ wk,
                                                       const float* __restrict__ wv,
                                                       float* __restrict__ qb,
                                                       float* __restrict__ kb,
                                                       float* __restrict__ vb) {
    extern __shared__ float cns[];
    int bid = blockIdx.x;
    int h = bid & 3;
    int t0 = (bid >> 2) * CN_T;
    int tid = threadIdx.x;
    int d = tid;
    int c = h * DHEAD + d;

#pragma unroll 3
    for (int p = 0; p < 3; p++) {
        float* dst = cns + p * (CN_R * 256);
        for (int i = tid; i < CN_R * 64; i += 256) {
            int row = i >> 6, d4 = (i & 63) << 2;
            int tt = t0 - 3 + row;
            float4 val = make_float4(0.f, 0.f, 0.f, 0.f);
            if (tt >= 0)
                val = *(const float4*)(qkvlin + (size_t)tt * NQKV + p * DMODEL +
                                       h * DHEAD + d4);
            *(float4*)&dst[row * 256 + d4] = val;
        }
    }
    __syncthreads();

    float wq0 = wq[c * 4], wq1 = wq[c * 4 + 1], wq2 = wq[c * 4 + 2], wq3 = wq[c * 4 + 3];
    float wk0 = wk[c * 4], wk1 = wk[c * 4 + 1], wk2 = wk[c * 4 + 2], wk3 = wk[c * 4 + 3];
    float wv0 = wv[c * 4], wv1 = wv[c * 4 + 1], wv2 = wv[c * 4 + 2], wv3 = wv[c * 4 + 3];

#pragma unroll 4
    for (int t = 0; t < CN_T; t++) {
        const float* sq = cns + CN_SQ + t * 256 + d;
        const float* sk = cns + CN_SK + t * 256 + d;
        const float* sv = cns + CN_SV + t * 256 + d;
        float aq = sq[0] * wq0 + sq[256] * wq1 + sq[512] * wq2 + sq[768] * wq3;
        float ak = sk[0] * wk0 + sk[256] * wk1 + sk[512] * wk2 + sk[768] * wk3;
        float av = sv[0] * wv0 + sv[256] * wv1 + sv[512] * wv2 + sv[768] * wv3;
        float qv = aq / (1.f + expf(-aq));
        float kv = ak / (1.f + expf(-ak));
        float vv = av / (1.f + expf(-av));
        cns[CN_QC + t * 256 + d] = qv;
        cns[CN_KC + t * 256 + d] = kv;
        vb[(size_t)(t0 + t) * DMODEL + c] = vv;
    }
    __syncthreads();

    int lane = tid & 31, warp = tid >> 5;
#pragma unroll
    for (int tt = warp; tt < CN_T; tt += 8) {
        float sq = 0.f, sk = 0.f;
#pragma unroll
        for (int i = lane; i < 256; i += 32) {
            float qv = cns[CN_QC + tt * 256 + i];
            float kv = cns[CN_KC + tt * 256 + i];
            sq = fmaf(qv, qv, sq);
            sk = fmaf(kv, kv, sk);
        }
#pragma unroll
        for (int off = 16; off; off >>= 1) {
            sq += __shfl_xor_sync(0xffffffffu, sq, off);
            sk += __shfl_xor_sync(0xffffffffu, sk, off);
        }
        if (lane == 0) { cns[CN_RED + tt] = sq; cns[CN_RED + 32 + tt] = sk; }
    }
    __syncthreads();

#pragma unroll 4
    for (int t = 0; t < CN_T; t++) {
        float rq = rsqrtf(cns[CN_RED + t] + 1e-6f);
        float rk = rsqrtf(cns[CN_RED + 32 + t] + 1e-6f);
        size_t o = (size_t)(t0 + t) * DMODEL + c;
        qb[o] = cns[CN_QC + t * 256 + d] * rq;
        kb[o] = cns[CN_KC + t * 256 + d] * rk;
    }
}

// ---- beta + gate probs v3: 4 timesteps/block, weight reads amortized ------
#define BG_T 4
__global__ __launch_bounds__(256) void beta_gate_kernel(const float* __restrict__ x,
                                                        const float* __restrict__ Wb,
                                                        const float* __restrict__ gate_w,
                                                        const float* __restrict__ gate_b,
                                                        const float* __restrict__ log_temp,
                                                        const float* __restrict__ eps_param,
                                                        float* __restrict__ beta_out,
                                                        float* __restrict__ probs_out) {
    __shared__ float sx[BG_T][DMODEL];
    __shared__ float sdot[24][BG_T];
    int t0 = blockIdx.x * BG_T;
    int tid = threadIdx.x;
    int warp = tid >> 5, lane = tid & 31;

#pragma unroll
    for (int i = tid; i < BG_T * DMODEL / 4; i += 256) {
        int t = i >> 8, d4 = (i & 255) << 2;
        *(float4*)&sx[t][d4] = *(const float4*)(x + (size_t)(t0 + t) * DMODEL + d4);
    }
    __syncthreads();

    for (int o = warp; o < 24; o += 8) {
        const float* wrow = (o < 4) ? (Wb + o * DMODEL) : (gate_w + (o - 4) * DMODEL);
        float s0 = 0.f, s1 = 0.f, s2 = 0.f, s3 = 0.f;
        for (int i = lane * 4; i < DMODEL; i += 128) {
            float4 wv = *(const float4*)&wrow[i];
            float4 x0 = *(const float4*)&sx[0][i];
            float4 x1 = *(const float4*)&sx[1][i];
            float4 x2 = *(const float4*)&sx[2][i];
            float4 x3 = *(const float4*)&sx[3][i];
            s0 = fmaf(wv.x, x0.x, fmaf(wv.y, x0.y, fmaf(wv.z, x0.z, fmaf(wv.w, x0.w, s0))));
            s1 = fmaf(wv.x, x1.x, fmaf(wv.y, x1.y, fmaf(wv.z, x1.z, fmaf(wv.w, x1.w, s1))));
            s2 = fmaf(wv.x, x2.x, fmaf(wv.y, x2.y, fmaf(wv.z, x2.z, fmaf(wv.w, x2.w, s2))));
            s3 = fmaf(wv.x, x3.x, fmaf(wv.y, x3.y, fmaf(wv.z, x3.z, fmaf(wv.w, x3.w, s3))));
        }
#pragma unroll
        for (int off = 16; off; off >>= 1) {
            s0 += __shfl_xor_sync(0xffffffffu, s0, off);
            s1 += __shfl_xor_sync(0xffffffffu, s1, off);
            s2 += __shfl_xor_sync(0xffffffffu, s2, off);
            s3 += __shfl_xor_sync(0xffffffffu, s3, off);
        }
        if (lane == 0) {
            sdot[o][0] = s0; sdot[o][1] = s1; sdot[o][2] = s2; sdot[o][3] = s3;
        }
    }
    __syncthreads();

    if (tid < BG_T * NH) {
        int t = tid >> 2, h = tid & 3;
        int tt = t0 + t;
        beta_out[tt * NH + h] = 1.f / (1.f + expf(-sdot[h][t]));
        float temp = expf(log_temp[h]);
        float lg[5], mx = -1e30f;
#pragma unroll
        for (int p = 0; p < 5; p++) {
            lg[p] = (sdot[4 + h * 5 + p][t] + gate_b[h * 5 + p]) / temp;
            mx = fmaxf(mx, lg[p]);
        }
        float se = 0.f;
#pragma unroll
        for (int p = 0; p < 5; p++) { lg[p] = expf(lg[p] - mx); se += lg[p]; }
        float eps = fminf(fmaxf(eps_param[h], 0.f), 0.2f);
#pragma unroll
        for (int p = 0; p < 5; p++)
            probs_out[(tt * NH + h) * 5 + p] = lg[p] / se * (1.f - 5.f * eps) + eps;
    }
}

// ---------------- per-chunk UT transform (parallel over chunks) ------------
#define CP_SMEM_FLOATS (2 * 32 * 260 + 2 * 32 * 33 + 32)
__global__ __launch_bounds__(256) void chunk_prep_kernel(const float* __restrict__ q,
                                                         const float* __restrict__ k,
                                                         const float* __restrict__ v,
                                                         const float* __restrict__ beta,
                                                         float* __restrict__ gu,
                                                         float* __restrict__ gw,
                                                         float* __restrict__ gattn) {
    extern __shared__ float smemf[];
    float (*sk)[260] = (float (*)[260])smemf;
    float (*sx)[260] = (float (*)[260])(smemf + 32 * 260);
    float (*sA)[33]  = (float (*)[33])(smemf + 2 * 32 * 260);
    float (*sT)[33]  = (float (*)[33])(smemf + 2 * 32 * 260 + 32 * 33);
    float* sbeta     = smemf + 2 * 32 * 260 + 2 * 32 * 33;

    int hb = blockIdx.x;
    int h = hb >> 6, ch = hb & 63;
    int t0 = ch * CSZ;
    int tid = threadIdx.x;

#pragma unroll
    for (int it = 0; it < 8; it++) {
        int i4 = tid + it * 256;
        int row = i4 >> 6, d4 = (i4 & 63) << 2;
        *(float4*)&sk[row][d4] =
            *(const float4*)(k + (size_t)(t0 + row) * DMODEL + h * DHEAD + d4);
    }
    if (tid < CSZ) sbeta[tid] = beta[(t0 + tid) * NH + h];
    __syncthreads();

#pragma unroll
    for (int p = tid; p < CSZ * CSZ; p += 256) {
        int i = p >> 5, j = p & 31;
        float a = 0.f;
        if (j < i) {
            float s0 = 0.f, s1 = 0.f;
#pragma unroll 8
            for (int d8 = 0; d8 < DHEAD; d8 += 8) {
                float4 x0 = *(const float4*)&sk[i][d8];
                float4 y0 = *(const float4*)&sk[j][d8];
                float4 x1 = *(const float4*)&sk[i][d8 + 4];
                float4 y1 = *(const float4*)&sk[j][d8 + 4];
                s0 = fmaf(x0.x, y0.x, fmaf(x0.y, y0.y,
                     fmaf(x0.z, y0.z, fmaf(x0.w, y0.w, s0))));
                s1 = fmaf(x1.x, y1.x, fmaf(x1.y, y1.y,
                     fmaf(x1.z, y1.z, fmaf(x1.w, y1.w, s1))));
            }
            a = -sbeta[i] * (s0 + s1);
        }
        sA[i][j] = a;
    }
    __syncthreads();

    if (tid < 32) {
        int col = tid;
        for (int i = 0; i < CSZ; i++) {
            float tv = (col == i) ? 1.f : 0.f;
            for (int j = 0; j < i; j++) tv += sA[i][j] * sT[j][col];
            sT[i][col] = tv;
            __syncwarp();
        }
    }
    __syncthreads();

#pragma unroll
    for (int it = 0; it < 8; it++) {
        int i4 = tid + it * 256;
        int row = i4 >> 6, d4 = (i4 & 63) << 2;
        float4 vv = *(const float4*)(v + (size_t)(t0 + row) * DMODEL + h * DHEAD + d4);
        float bb = sbeta[row];
        vv.x *= bb; vv.y *= bb; vv.z *= bb; vv.w *= bb;
        *(float4*)&sx[row][d4] = vv;
    }
    __syncthreads();

    {
        int d = tid;
        float acc[32];
#pragma unroll
        for (int i = 0; i < 32; i++) acc[i] = 0.f;
#pragma unroll
        for (int j = 0; j < 32; j++) {
            float xv = sx[j][d];
#pragma unroll
            for (int i = j; i < 32; i++) acc[i] = fmaf(sT[i][j], xv, acc[i]);
        }
#pragma unroll
        for (int i = 0; i < 32; i++)
            gu[(t0 + i) * DMODEL + h * DHEAD + d] = acc[i];
#pragma unroll
        for (int i = 0; i < 32; i++) acc[i] = 0.f;
#pragma unroll
        for (int j = 0; j < 32; j++) {
            float xv = sbeta[j] * sk[j][d];
#pragma unroll
            for (int i = j; i < 32; i++) acc[i] = fmaf(sT[i][j], xv, acc[i]);
        }
#pragma unroll
        for (int i = 0; i < 32; i++)
            gw[(t0 + i) * DMODEL + h * DHEAD + d] = acc[i];
    }
    __syncthreads();

#pragma unroll
    for (int it = 0; it < 8; it++) {
        int i4 = tid + it * 256;
        int row = i4 >> 6, d4 = (i4 & 63) << 2;
        *(float4*)&sx[row][d4] =
            *(const float4*)(q + (size_t)(t0 + row) * DMODEL + h * DHEAD + d4);
    }
    __syncthreads();
#pragma unroll
    for (int p = tid; p < CSZ * CSZ; p += 256) {
        int i = p >> 5, j = p & 31;
        float a = 0.f;
        if (j <= i) {
            float s0 = 0.f, s1 = 0.f;
#pragma unroll 8
            for (int d8 = 0; d8 < DHEAD; d8 += 8) {
                float4 x0 = *(const float4*)&sx[i][d8];
                float4 y0 = *(const float4*)&sk[j][d8];
                float4 x1 = *(const float4*)&sx[i][d8 + 4];
                float4 y1 = *(const float4*)&sk[j][d8 + 4];
                s0 = fmaf(x0.x, y0.x, fmaf(x0.y, y0.y,
                     fmaf(x0.z, y0.z, fmaf(x0.w, y0.w, s0))));
                s1 = fmaf(x1.x, y1.x, fmaf(x1.y, y1.y,
                     fmaf(x1.z, y1.z, fmaf(x1.w, y1.w, s1))));
            }
            a = s0 + s1;
        }
        gattn[(hb * CSZ + i) * CSZ + j] = a;
    }
}

// ---------------- sequential chunk scan, cp.async double-buffered ----------
#define SD_TILE   (32 * 260)
#define SD_BUF    (3 * SD_TILE)
#define SD_SC     (2 * SD_BUF)
#define SD_SU     (SD_SC + 8 * 260)
#define SD_SATT   (SD_SU + 2 * 256)
#define SD_SUA    (SD_SATT + 2 * 1024)
#define SCAN_SMEM_FLOATS (SD_SUA + 256)
__global__ __launch_bounds__(256) void delta_scan_kernel(const float* __restrict__ q,
                                                         const float* __restrict__ k,
                                                         const float* __restrict__ w,
                                                         const float* __restrict__ u,
                                                         const float* __restrict__ attn,
                                                         float* __restrict__ dout) {
    extern __shared__ float smemf[];
    unsigned sb;
    asm("{ .reg .u64 t; cvta.to.shared.u64 t, %1; cvt.u32.u64 %0, t; }"
        : "=r"(sb) : "l"(smemf));

    int b = blockIdx.x;
    int h = b >> 5, sl = b & 31;
    int tid = threadIdx.x;
    int r = tid >> 3, c = tid & 7;
    int cbase = h * DHEAD + sl * 8;

#define SD_ISSUE(ch, bf)                                                            \
    do {                                                                            \
        int t0i = (ch) * CSZ;                                                       \
        unsigned qo = sb + ((bf) * SD_BUF) * 4;                                     \
        _Pragma("unroll")                                                           \
        for (int it = 0; it < 8; it++) {                                            \
            int i4 = tid + it * 256;                                                \
            int row = i4 >> 6, d4 = (i4 & 63) << 2;                                 \
            size_t gidx = (size_t)(t0i + row) * DMODEL + h * DHEAD + d4;            \
            unsigned so = qo + (row * 260 + d4) * 4;                                \
            cp16(so, q + gidx);                                                     \
            cp16(so + SD_TILE * 4, k + gidx);                                       \
            cp16(so + 2 * SD_TILE * 4, w + gidx);                                   \
        }                                                                           \
        cp4(sb + (SD_SU + (bf) * 256 + tid) * 4,                                    \
            u + (size_t)(t0i + r) * DMODEL + cbase + c);                            \
        cp16(sb + (SD_SATT + (bf) * 1024 + tid * 4) * 4,                            \
             attn + (size_t)(h * NCHUNK + (ch)) * 1024 + tid * 4);                  \
        asm volatile("cp.async.commit_group;" ::: "memory");                        \
    } while (0)

    float Sreg[8];
#pragma unroll
    for (int i = 0; i < 8; i++) Sreg[i] = 0.f;

    SD_ISSUE(0, 0);
    int buf = 0;
    for (int ch = 0; ch < NCHUNK; ch++) {
        // publish S (independent of incoming tiles) before issuing/waiting
#pragma unroll
        for (int i = 0; i < 8; i++) smemf[SD_SC + i * 260 + tid] = Sreg[i];
        if (ch + 1 < NCHUNK) {
            SD_ISSUE(ch + 1, buf ^ 1);
            asm volatile("cp.async.wait_group 1;" ::: "memory");
        } else {
            asm volatile("cp.async.wait_group 0;" ::: "memory");
        }
        __syncthreads();

        const float* sq  = smemf + buf * SD_BUF;
        const float* skk = sq + SD_TILE;
        const float* sw  = sq + 2 * SD_TILE;
        const float* su  = smemf + SD_SU + buf * 256;
        const float* satt = smemf + SD_SATT + buf * 1024;
        float* sua = smemf + SD_SUA;

        float au0 = 0.f, au1 = 0.f, au2 = 0.f, au3 = 0.f;
        float ao0 = 0.f, ao1 = 0.f, ao2 = 0.f, ao3 = 0.f;
        const float* scc = smemf + SD_SC + c * 260;
        const float* swr = sw + r * 260;
        const float* sqr = sq + r * 260;
#pragma unroll 4
        for (int d16 = 0; d16 < DHEAD; d16 += 16) {
            float4 sv0 = *(const float4*)&scc[d16];
            float4 wv0 = *(const float4*)&swr[d16];
            float4 qv0 = *(const float4*)&sqr[d16];
            float4 sv1 = *(const float4*)&scc[d16 + 4];
            float4 wv1 = *(const float4*)&swr[d16 + 4];
            float4 qv1 = *(const float4*)&sqr[d16 + 4];
            float4 sv2 = *(const float4*)&scc[d16 + 8];
            float4 wv2 = *(const float4*)&swr[d16 + 8];
            float4 qv2 = *(const float4*)&sqr[d16 + 8];
            float4 sv3 = *(const float4*)&scc[d16 + 12];
            float4 wv3 = *(const float4*)&swr[d16 + 12];
            float4 qv3 = *(const float4*)&sqr[d16 + 12];
            au0 = fmaf(wv0.x, sv0.x, fmaf(wv0.y, sv0.y,
                  fmaf(wv0.z, sv0.z, fmaf(wv0.w, sv0.w, au0))));
            au1 = fmaf(wv1.x, sv1.x, fmaf(wv1.y, sv1.y,
                  fmaf(wv1.z, sv1.z, fmaf(wv1.w, sv1.w, au1))));
            au2 = fmaf(wv2.x, sv2.x, fmaf(wv2.y, sv2.y,
                  fmaf(wv2.z, sv2.z, fmaf(wv2.w, sv2.w, au2))));
            au3 = fmaf(wv3.x, sv3.x, fmaf(wv3.y, sv3.y,
                  fmaf(wv3.z, sv3.z, fmaf(wv3.w, sv3.w, au3))));
            ao0 = fmaf(qv0.x, sv0.x, fmaf(qv0.y, sv0.y,
                  fmaf(qv0.z, sv0.z, fmaf(qv0.w, sv0.w, ao0))));
            ao1 = fmaf(qv1.x, sv1.x, fmaf(qv1.y, sv1.y,
                  fmaf(qv1.z, sv1.z, fmaf(qv1.w, sv1.w, ao1))));
            ao2 = fmaf(qv2.x, sv2.x, fmaf(qv2.y, sv2.y,
                  fmaf(qv2.z, sv2.z, fmaf(qv2.w, sv2.w, ao2))));
            ao3 = fmaf(qv3.x, sv3.x, fmaf(qv3.y, sv3.y,
                  fmaf(qv3.z, sv3.z, fmaf(qv3.w, sv3.w, ao3))));
        }
        float au = su[tid] - ((au0 + au1) + (au2 + au3));
        float ao = (ao0 + ao1) + (ao2 + ao3);
        sua[tid] = au;
        __syncthreads();

#pragma unroll
        for (int j4 = 0; j4 < CSZ; j4 += 4) {
            float4 at = *(const float4*)&satt[r * CSZ + j4];
            ao = fmaf(at.x, sua[(j4 + 0) * 8 + c], ao);
            ao = fmaf(at.y, sua[(j4 + 1) * 8 + c], ao);
            ao = fmaf(at.z, sua[(j4 + 2) * 8 + c], ao);
            ao = fmaf(at.w, sua[(j4 + 3) * 8 + c], ao);
        }
        dout[(size_t)(ch * CSZ + r) * DMODEL + cbase + c] = ao;

#pragma unroll 8
        for (int j = 0; j < CSZ; j++) {
            float kv = skk[j * 260 + tid];
            float4 u0 = *(const float4*)&sua[j * 8];
            float4 u1 = *(const float4*)&sua[j * 8 + 4];
            Sreg[0] = fmaf(kv, u0.x, Sreg[0]);
            Sreg[1] = fmaf(kv, u0.y, Sreg[1]);
            Sreg[2] = fmaf(kv, u0.z, Sreg[2]);
            Sreg[3] = fmaf(kv, u0.w, Sreg[3]);
            Sreg[4] = fmaf(kv, u1.x, Sreg[4]);
            Sreg[5] = fmaf(kv, u1.y, Sreg[5]);
            Sreg[6] = fmaf(kv, u1.z, Sreg[6]);
            Sreg[7] = fmaf(kv, u1.w, Sreg[7]);
        }
        __syncthreads();
        buf ^= 1;
    }
#undef SD_ISSUE
}

// ---------------- FIR + gated mix + RMSNorm, t-tiled; fp16 hi/lo output ----
#define CT 16
#define VR (CT + 62)
#define CMB_SMEM_FLOATS (256 * 81 + 256 * 81 + 80 + 4096 + 16)
__global__ __launch_bounds__(256) void combine_kernel(const float* __restrict__ v,
                                                      const float* __restrict__ delta,
                                                      const float* __restrict__ probs,
                                                      const float* __restrict__ fs,
                                                      const float* __restrict__ fm,
                                                      const float* __restrict__ fl,
                                                      const float* __restrict__ normw,
                                                      __half* __restrict__ outh,
                                                      __half* __restrict__ outl) {
    extern __shared__ float cs[];
    float (*vsm)[81] = (float (*)[81])cs;
    float (*fsm)[81] = (float (*)[81])(cs + 256 * 81);
    float* psm = cs + 2 * 256 * 81;
    float* sqm = psm + 80;
    float* red = sqm + 4096;

    int bid = blockIdx.x;
    int h = bid & 3;
    int tt0 = (bid >> 2) * CT;
    int tid = threadIdx.x;
    int d = tid;

    const float* flh = fl + h * 256 * 63;
    for (int f = tid; f < 256 * 63; f += 256) {
        int dd = f / 63;
        fsm[dd][f - dd * 63] = flh[f];
    }
    const float* fmh = fm + h * 256 * 15;
    for (int f = tid; f < 256 * 15; f += 256) {
        int dd = f / 15;
        fsm[dd][63 + f - dd * 15] = fmh[f];
    }
    const float* fsh = fs + h * 256 * 3;
    for (int f = tid; f < 256 * 3; f += 256) {
        int dd = f / 3;
        fsm[dd][78 + f - dd * 3] = fsh[f];
    }
    if (tid < CT * 5)
        psm[tid] = probs[(tt0 * NH + h) * 5 + (tid / 5) * (NH * 5) + (tid % 5)];
    for (int L = 0; L < VR; L++) {
        int tt = tt0 - 62 + L;
        vsm[tid][L] = (tt >= 0) ? v[(size_t)tt * DMODEL + h * DHEAD + tid] : 0.f;
    }
    __syncthreads();

    float aL[CT], aM[CT], aS[CT];
#pragma unroll
    for (int t = 0; t < CT; t++) { aL[t] = 0.f; aM[t] = 0.f; aS[t] = 0.f; }

    for (int kk = 0; kk < 63; kk++) {
        float fv = fsm[d][kk];
#pragma unroll
        for (int t = 0; t < CT; t++) aL[t] = fmaf(vsm[d][kk + t], fv, aL[t]);
    }
#pragma unroll
    for (int kk = 0; kk < 15; kk++) {
        float fv = fsm[d][63 + kk];
#pragma unroll
        for (int t = 0; t < CT; t++) aM[t] = fmaf(vsm[d][48 + kk + t], fv, aM[t]);
    }
#pragma unroll
    for (int kk = 0; kk < 3; kk++) {
        float fv = fsm[d][78 + kk];
#pragma unroll
        for (int t = 0; t < CT; t++) aS[t] = fmaf(vsm[d][60 + kk + t], fv, aS[t]);
    }

    float mixv[CT];
#pragma unroll
    for (int t = 0; t < CT; t++) {
        float dlv = delta[(size_t)(tt0 + t) * DMODEL + h * DHEAD + d];
        const float* pb = psm + t * 5;
        float vcur = vsm[d][62 + t];
        mixv[t] = pb[0] * aS[t] + pb[1] * aM[t] + pb[2] * aL[t] +
                  pb[3] * dlv + pb[4] * vcur;
        sqm[t * 256 + d] = mixv[t] * mixv[t];
    }
    __syncthreads();

    int lane = tid & 31, warp = tid >> 5;
#pragma unroll
    for (int tt = warp; tt < CT; tt += 8) {
        float s = 0.f;
#pragma unroll
        for (int i = lane; i < 256; i += 32) s += sqm[tt * 256 + i];
#pragma unroll
        for (int off = 16; off; off >>= 1) s += __shfl_xor_sync(0xffffffffu, s, off);
        if (lane == 0) red[tt] = s;
    }
    __syncthreads();

    float nw = normw[d];
#pragma unroll
    for (int t = 0; t < CT; t++) {
        float val = mixv[t] * rsqrtf(red[t] * (1.f / 256.f) + 1e-5f) * nw;
        __half hv = __float2half_rn(val);
        size_t o = (size_t)(tt0 + t) * DMODEL + h * DHEAD + d;
        outh[o] = hv;
        outl[o] = __float2half_rn(val - __half2float(hv));
    }
}

// ---------------- launch ---------------------------------------------------
extern "C" void kernel_launch(void* const* d_in, const int* in_sizes, int n_in,
                              void* d_out, int out_size) {
    const float* x       = (const float*)d_in[0];
    const float* Wq      = (const float*)d_in[1];
    const float* Wk      = (const float*)d_in[2];
    const float* Wv      = (const float*)d_in[3];
    const float* Wb      = (const float*)d_in[4];
    const float* conv_q  = (const float*)d_in[5];
    const float* conv_k  = (const float*)d_in[6];
    const float* conv_v  = (const float*)d_in[7];
    const float* fir_s   = (const float*)d_in[8];
    const float* fir_m   = (const float*)d_in[9];
    const float* fir_l   = (const float*)d_in[10];
    const float* gate_w  = (const float*)d_in[11];
    const float* gate_b  = (const float*)d_in[12];
    const float* log_tmp = (const float*)d_in[13];
    const float* eps_p   = (const float*)d_in[14];
    const float* norm_w  = (const float*)d_in[15];
    const float* Wo      = (const float*)d_in[16];
    float* out = (float*)d_out;

    float *qkvlin, *qb, *kb, *vb, *ub, *wb, *db, *betab, *probsb, *attnb;
    cudaGetSymbolAddress((void**)&qkvlin, g_qkvlin);
    cudaGetSymbolAddress((void**)&qb,    g_q);
    cudaGetSymbolAddress((void**)&kb,    g_k);
    cudaGetSymbolAddress((void**)&vb,    g_v);
    cudaGetSymbolAddress((void**)&ub,    g_u);
    cudaGetSymbolAddress((void**)&wb,    g_w);
    cudaGetSymbolAddress((void**)&db,    g_delta);
    cudaGetSymbolAddress((void**)&betab, g_beta);
    cudaGetSymbolAddress((void**)&probsb, g_probs);
    cudaGetSymbolAddress((void**)&attnb, g_attn);

    __half *xh, *xl, *wqkv, *wo, *mixh, *mixl;
    cudaGetSymbolAddress((void**)&xh, g_xh);
    cudaGetSymbolAddress((void**)&xl, g_xl);
    cudaGetSymbolAddress((void**)&wqkv, g_wqkv);
    cudaGetSymbolAddress((void**)&wo, g_wo);
    cudaGetSymbolAddress((void**)&mixh, g_mixh);
    cudaGetSymbolAddress((void**)&mixl, g_mixl);

    cudaFuncSetAttribute(hgemm_nt, cudaFuncAttributeMaxDynamicSharedMemorySize, HG_SMEM);
    cudaFuncSetAttribute(convnorm_kernel, cudaFuncAttributeMaxDynamicSharedMemorySize,
                         CN_SMEM_FLOATS * 4);
    cudaFuncSetAttribute(chunk_prep_kernel, cudaFuncAttributeMaxDynamicSharedMemorySize,
                         CP_SMEM_FLOATS * 4);
    cudaFuncSetAttribute(delta_scan_kernel, cudaFuncAttributeMaxDynamicSharedMemorySize,
                         SCAN_SMEM_FLOATS * 4);
    cudaFuncSetAttribute(combine_kernel, cudaFuncAttributeMaxDynamicSharedMemorySize,
                         CMB_SMEM_FLOATS * 4);

    int nX4 = SEQ * DMODEL / 4;
    int nW4 = DMODEL * DMODEL / 4;

    split_kernel<<<(nX4 + 255) / 256, 256>>>(x, xh, xl, nX4);                 // 0
    wsplit_kernel<<<(nW4 + 255) / 256, 256>>>(Wq, Wk, Wv, Wo, wqkv, wo);      // 1
    dim3 tg3(NQKV / 128, SEQ / 128);                                          // (24,16)
    hgemm_nt<<<tg3, 256, HG_SMEM>>>(xh, xl, wqkv, qkvlin, SEQ, NQKV, DMODEL); // 2
    convnorm_kernel<<<(SEQ / CN_T) * NH, 256, CN_SMEM_FLOATS * 4>>>(
        qkvlin, conv_q, conv_k, conv_v, qb, kb, vb);                          // 3 (ncu)
    beta_gate_kernel<<<SEQ / BG_T, 256>>>(x, Wb, gate_w, gate_b, log_tmp, eps_p,
                                          betab, probsb);                     // 4
    chunk_prep_kernel<<<NH * NCHUNK, 256, CP_SMEM_FLOATS * 4>>>(qb, kb, vb, betab,
                                                                ub, wb, attnb);
    delta_scan_kernel<<<NH * 32, 256, SCAN_SMEM_FLOATS * 4>>>(qb, kb, wb, ub,
                                                              attnb, db);
    combine_kernel<<<(SEQ / CT) * NH, 256, CMB_SMEM_FLOATS * 4>>>(
        vb, db, probsb, fir_s, fir_m, fir_l, norm_w, mixh, mixl);
    dim3 tg1(DMODEL / 128, SEQ / 128);                                        // (8,16)
    hgemm_nt<<<tg1, 256, HG_SMEM>>>(mixh, mixl, wo, out, SEQ, DMODEL, DMODEL);
}